// round 2
// baseline (speedup 1.0000x reference)
#include <cuda_runtime.h>
#include <cstdint>

// Scatter: out[fault_idx[i]] = fault_vals[i]. Indices are unique, so no races.
__global__ void fault_scatter_kernel(const float* __restrict__ vals,
                                     const int* __restrict__ idx,
                                     float* __restrict__ out,
                                     int n) {
    int i = blockIdx.x * blockDim.x + threadIdx.x;
    if (i < n) {
        out[idx[i]] = vals[i];
    }
}

extern "C" void kernel_launch(void* const* d_in, const int* in_sizes, int n_in,
                              void* d_out, int out_size) {
    const float* x          = (const float*)d_in[0];
    const float* fault_vals = (const float*)d_in[1];
    const int*   fault_idx  = (const int*)d_in[2];
    float* out = (float*)d_out;

    const int numel   = in_sizes[0];   // 67,108,864
    const int covered = in_sizes[1];   // 671,089

    // 1) Bulk copy x -> out (HBM-bound; D2D async memcpy hits near-peak BW).
    cudaMemcpyAsync(out, x, (size_t)numel * sizeof(float),
                    cudaMemcpyDeviceToDevice);

    // 2) Scatter faults on the same stream (ordered after the copy).
    const int threads = 256;
    const int blocks  = (covered + threads - 1) / threads;
    fault_scatter_kernel<<<blocks, threads>>>(fault_vals, fault_idx, out, covered);
}